// round 2
// baseline (speedup 1.0000x reference)
#include <cuda_runtime.h>

#define CH      30
#define CELLS   256
#define THREADS 256
#define GRID    456   // 152 SMs x 3 blocks (smem-limited occupancy)

// Deterministic scratch for per-block partial sums (no device-side allocation).
__device__ float g_partials[GRID];

__device__ __forceinline__ float warp_reduce(float v) {
#pragma unroll
    for (int o = 16; o > 0; o >>= 1) v += __shfl_xor_sync(0xffffffffu, v, o);
    return v;
}

__global__ void __launch_bounds__(THREADS)
yolo_main(const float* __restrict__ pred, const float* __restrict__ targ, int n_cells) {
    extern __shared__ float sm[];
    float* sp = sm;               // CELLS*CH pred floats
    float* st = sm + CELLS * CH;  // CELLS*CH target floats

    const int tid = threadIdx.x;
    const int n_tiles = (n_cells + CELLS - 1) / CELLS;
    float acc = 0.f;

    for (int tile = blockIdx.x; tile < n_tiles; tile += gridDim.x) {
        const int cell0 = tile * CELLS;
        const int ncell = min(CELLS, n_cells - cell0);
        const int nflt  = ncell * CH;
        const long long base = (long long)cell0 * CH;

        __syncthreads();  // previous tile's compute must finish before overwrite

        // Fully coalesced float4 staging: GMEM -> SMEM
        const float4* p4 = reinterpret_cast<const float4*>(pred + base);
        const float4* t4 = reinterpret_cast<const float4*>(targ + base);
        const int nv4 = nflt >> 2;
        for (int k = tid; k < nv4; k += THREADS) {
            reinterpret_cast<float4*>(sp)[k] = p4[k];
            reinterpret_cast<float4*>(st)[k] = t4[k];
        }
        for (int k = (nv4 << 2) + tid; k < nflt; k += THREADS) {  // scalar tail
            sp[k] = pred[base + k];
            st[k] = targ[base + k];
        }
        __syncthreads();

        if (tid < ncell) {
            const float* p = sp + tid * CH;
            const float* t = st + tid * CH;

            // IoU of both pred boxes vs the target box
            const float tx0 = t[0], ty0 = t[1], tx1 = t[2], ty1 = t[3];
            const float area2 = (tx1 - tx0) * (ty1 - ty0);
            float iou0, iou1;
#pragma unroll
            for (int b = 0; b < 2; b++) {
                const int o = b * 5;
                const float x0 = p[o + 0], y0 = p[o + 1];
                const float x1 = p[o + 2], y1 = p[o + 3];
                float w = fminf(x1, tx1) - fmaxf(x0, tx0);
                float h = fminf(y1, ty1) - fmaxf(y0, ty0);
                w = fmaxf(w, 0.f);
                h = fmaxf(h, 0.f);
                const float inter = w * h;
                const float area1 = (x1 - x0) * (y1 - y0);
                const float iou = inter / (area1 + area2 - inter);
                if (b == 0) iou0 = iou; else iou1 = iou;
            }
            // argmax with first-index tiebreak: box 0 wins unless iou1 strictly greater
            const int o = (iou1 > iou0) ? 5 : 0;

            const float dx = p[o + 0] - t[o + 0];
            const float dy = p[o + 1] - t[o + 1];
            const float l1 = dx * dx + dy * dy;

            const float dw = sqrtf(p[o + 2]) - sqrtf(t[o + 2]);
            const float dh = sqrtf(p[o + 3]) - sqrtf(t[o + 3]);
            const float l2 = dw * dw + dh * dh;

            const float dc = p[o + 4] - t[o + 4];
            const float conf = dc * dc;

            float s5 = 0.f;
#pragma unroll
            for (int c = 10; c < 30; c++) {
                const float d = p[c] - t[c];
                s5 += d * d;
            }

            const float t4v = t[4];
            float L;
            if (t4v > 0.f)        L = 5.0f * (l1 + l2) + conf + s5;  // obj
            else if (t4v == 0.f)  L = 0.5f * conf;                   // noobj
            else                  L = 0.f;
            acc += L;
        }
    }

    // Block reduction (reuse smem after final sync)
    __syncthreads();
    float w = warp_reduce(acc);
    if ((tid & 31) == 0) sp[tid >> 5] = w;
    __syncthreads();
    if (tid < 32) {
        float v = (tid < (THREADS / 32)) ? sp[tid] : 0.f;
        v = warp_reduce(v);
        if (tid == 0) g_partials[blockIdx.x] = v;
    }
}

__global__ void yolo_reduce(float* __restrict__ out, int out_size) {
    __shared__ float s[32];
    const int tid = threadIdx.x;
    float v = (tid < GRID) ? g_partials[tid] : 0.f;
    v = warp_reduce(v);
    if ((tid & 31) == 0) s[tid >> 5] = v;
    __syncthreads();
    if (tid < 32) {
        float x = (tid < (int)(blockDim.x / 32)) ? s[tid] : 0.f;
        x = warp_reduce(x);
        if (tid == 0) out[0] = x;
    }
    // d_out is poisoned; clear any extra elements
    for (int i = tid + 1; i < out_size; i += blockDim.x) out[i] = 0.f;
}

extern "C" void kernel_launch(void* const* d_in, const int* in_sizes, int n_in,
                              void* d_out, int out_size) {
    const float* pred = (const float*)d_in[0];
    const float* targ = (const float*)d_in[1];
    float* out = (float*)d_out;
    const int n_cells = in_sizes[0] / CH;

    const size_t smem = (size_t)CELLS * CH * 2 * sizeof(float);  // 61440 B
    cudaFuncSetAttribute(yolo_main, cudaFuncAttributeMaxDynamicSharedMemorySize, (int)smem);

    yolo_main<<<GRID, THREADS, smem>>>(pred, targ, n_cells);
    yolo_reduce<<<1, 512>>>(out, out_size);
}

// round 4
// speedup vs baseline: 1.0814x; 1.0814x over previous
#include <cuda_runtime.h>

#define CH          30
#define CELLS       128
#define THREADS     128
#define GRID        448                  // 12544 tiles / 448 = exactly 28 tiles per block
#define TILE_FLOATS (CELLS * CH)         // 3840 floats = 15360 B per array per tile
#define TILE_V4     (TILE_FLOATS / 4)    // 960 float4 per array per tile
#define STAGE_FLOATS (2 * TILE_FLOATS)   // pred + target per stage = 30720 B

// Deterministic scratch (no device-side allocation).
__device__ float        g_partials[GRID];
__device__ unsigned int g_count = 0;     // self-resetting mod GRID across graph replays

__device__ __forceinline__ void cp16(void* smem_dst, const void* gmem_src) {
    unsigned int d = (unsigned int)__cvta_generic_to_shared(smem_dst);
    asm volatile("cp.async.cg.shared.global [%0], [%1], 16;\n" :: "r"(d), "l"(gmem_src));
}
__device__ __forceinline__ void cp_commit() { asm volatile("cp.async.commit_group;\n" ::: "memory"); }
__device__ __forceinline__ void cp_wait1()  { asm volatile("cp.async.wait_group 1;\n" ::: "memory"); }

__device__ __forceinline__ float warp_reduce(float v) {
#pragma unroll
    for (int o = 16; o > 0; o >>= 1) v += __shfl_xor_sync(0xffffffffu, v, o);
    return v;
}

__global__ void __launch_bounds__(THREADS)
yolo_fused(const float* __restrict__ pred, const float* __restrict__ targ,
           int n_tiles, float* __restrict__ out, int out_size) {
    extern __shared__ float sm[];   // 2 stages x (pred tile + target tile) = 61440 B
    const int tid = threadIdx.x;
    const int bid = blockIdx.x;

    // Tiles for this block: tile = bid + i*GRID, i in [0, iters)
    const int iters = (n_tiles - bid + GRID - 1) / GRID;

    // ---- pipelined staging -------------------------------------------------
    auto load_stage = [&](int i, int stage) {
        if (i < iters) {
            const long long tile = bid + (long long)i * GRID;
            const float4* p4 = reinterpret_cast<const float4*>(pred + tile * TILE_FLOATS);
            const float4* t4 = reinterpret_cast<const float4*>(targ + tile * TILE_FLOATS);
            float4* sp = reinterpret_cast<float4*>(sm + stage * STAGE_FLOATS);
            float4* st = reinterpret_cast<float4*>(sm + stage * STAGE_FLOATS + TILE_FLOATS);
            for (int k = tid; k < TILE_V4; k += THREADS) {
                cp16(sp + k, p4 + k);
                cp16(st + k, t4 + k);
            }
        }
        cp_commit();  // commit (possibly empty) group to keep wait arithmetic uniform
    };

    load_stage(0, 0);
    load_stage(1, 1);

    float acc = 0.f;
    for (int i = 0; i < iters; i++) {
        const int stage = i & 1;
        cp_wait1();          // stage i's group complete (<=1 group pending)
        __syncthreads();     // all threads' copies for stage i visible block-wide

        const float* p = sm + stage * STAGE_FLOATS + tid * CH;
        const float* t = sm + stage * STAGE_FLOATS + TILE_FLOATS + tid * CH;

        // IoU of both pred boxes vs the target box
        const float tx0 = t[0], ty0 = t[1], tx1 = t[2], ty1 = t[3];
        const float area2 = (tx1 - tx0) * (ty1 - ty0);
        float iou0, iou1;
#pragma unroll
        for (int b = 0; b < 2; b++) {
            const int o = b * 5;
            const float x0 = p[o + 0], y0 = p[o + 1];
            const float x1 = p[o + 2], y1 = p[o + 3];
            float w = fminf(x1, tx1) - fmaxf(x0, tx0);
            float h = fminf(y1, ty1) - fmaxf(y0, ty0);
            w = fmaxf(w, 0.f);
            h = fmaxf(h, 0.f);
            const float inter = w * h;
            const float area1 = (x1 - x0) * (y1 - y0);
            const float iou = inter / (area1 + area2 - inter);
            if (b == 0) iou0 = iou; else iou1 = iou;
        }
        // argmax with first-index tiebreak: box 0 wins unless iou1 strictly greater
        const int o = (iou1 > iou0) ? 5 : 0;

        const float dx = p[o + 0] - t[o + 0];
        const float dy = p[o + 1] - t[o + 1];
        const float l1 = dx * dx + dy * dy;

        const float dw = sqrtf(p[o + 2]) - sqrtf(t[o + 2]);
        const float dh = sqrtf(p[o + 3]) - sqrtf(t[o + 3]);
        const float l2 = dw * dw + dh * dh;

        const float dc = p[o + 4] - t[o + 4];
        const float conf = dc * dc;

        float s5 = 0.f;
#pragma unroll
        for (int c = 10; c < 30; c++) {
            const float d = p[c] - t[c];
            s5 += d * d;
        }

        const float t4v = t[4];
        float L;
        if (t4v > 0.f)       L = 5.0f * (l1 + l2) + conf + s5;  // obj
        else if (t4v == 0.f) L = 0.5f * conf;                   // noobj
        else                 L = 0.f;
        acc += L;

        __syncthreads();          // everyone done with stage before overwrite
        load_stage(i + 2, stage); // prefetch two tiles ahead into freed stage
    }

    // ---- block reduction ---------------------------------------------------
    __syncthreads();              // smem free for reuse
    float w = warp_reduce(acc);
    if ((tid & 31) == 0) sm[tid >> 5] = w;
    __syncthreads();
    __shared__ bool s_last;
    if (tid == 0) {
        float v = 0.f;
#pragma unroll
        for (int j = 0; j < THREADS / 32; j++) v += sm[j];
        g_partials[bid] = v;
        __threadfence();
        unsigned int old = atomicAdd(&g_count, 1u);
        s_last = (((old + 1u) % GRID) == 0u);   // wraps -> valid on every graph replay
    }
    __syncthreads();

    // ---- last block finishes the reduction (deterministic order) -----------
    if (s_last) {
        __threadfence();
        float v = 0.f;
        for (int k = tid; k < GRID; k += THREADS) v += g_partials[k];
        v = warp_reduce(v);
        if ((tid & 31) == 0) sm[tid >> 5] = v;
        __syncthreads();
        if (tid == 0) {
            float tot = 0.f;
#pragma unroll
            for (int j = 0; j < THREADS / 32; j++) tot += sm[j];
            out[0] = tot;
        }
        // d_out is poisoned to 0xAA; clear any extra elements
        for (int k = tid + 1; k < out_size; k += THREADS) out[k] = 0.f;
    }
}

extern "C" void kernel_launch(void* const* d_in, const int* in_sizes, int n_in,
                              void* d_out, int out_size) {
    const float* pred = (const float*)d_in[0];
    const float* targ = (const float*)d_in[1];
    float* out = (float*)d_out;
    const int n_cells = in_sizes[0] / CH;     // 1,605,632
    const int n_tiles = n_cells / CELLS;      // 12,544 (exact)

    const size_t smem = (size_t)2 * STAGE_FLOATS * sizeof(float);  // 61440 B
    cudaFuncSetAttribute(yolo_fused, cudaFuncAttributeMaxDynamicSharedMemorySize, (int)smem);

    yolo_fused<<<GRID, THREADS, smem>>>(pred, targ, n_tiles, out, out_size);
}

// round 5
// speedup vs baseline: 1.0908x; 1.0087x over previous
#include <cuda_runtime.h>

#define CH           30
#define CELLS        64
#define THREADS      128
#define STAGES       4
#define GRID         448                  // 25088 tiles / 448 = exactly 56 per block
#define TILE_FLOATS  (CELLS * CH)         // 1920 floats = 7680 B per array per tile
#define TILE_V4      (TILE_FLOATS / 4)    // 480 float4 per array per tile
#define STAGE_FLOATS (2 * TILE_FLOATS)    // pred + target per stage = 15360 B

// Deterministic scratch (no device-side allocation).
__device__ float        g_partials[GRID];
__device__ unsigned int g_count = 0;      // self-resetting mod GRID across graph replays

__device__ __forceinline__ void cp16(void* smem_dst, const void* gmem_src) {
    unsigned int d = (unsigned int)__cvta_generic_to_shared(smem_dst);
    asm volatile("cp.async.cg.shared.global [%0], [%1], 16;\n" :: "r"(d), "l"(gmem_src));
}
__device__ __forceinline__ void cp_commit() { asm volatile("cp.async.commit_group;\n" ::: "memory"); }
__device__ __forceinline__ void cp_wait2()  { asm volatile("cp.async.wait_group 2;\n" ::: "memory"); }

__device__ __forceinline__ float warp_reduce(float v) {
#pragma unroll
    for (int o = 16; o > 0; o >>= 1) v += __shfl_xor_sync(0xffffffffu, v, o);
    return v;
}

__global__ void __launch_bounds__(THREADS)
yolo_fused(const float* __restrict__ pred, const float* __restrict__ targ,
           int n_tiles, float* __restrict__ out, int out_size) {
    extern __shared__ float sm[];   // STAGES x (pred tile + target tile) = 61440 B
    const int tid = threadIdx.x;
    const int bid = blockIdx.x;

    // Tiles for this block: tile = bid + i*GRID, i in [0, iters)  (iters == 56 for all)
    const int iters = (n_tiles - bid + GRID - 1) / GRID;

    auto load_stage = [&](int i, int stage) {
        if (i < iters) {
            const long long tile = bid + (long long)i * GRID;
            const float4* p4 = reinterpret_cast<const float4*>(pred + tile * TILE_FLOATS);
            const float4* t4 = reinterpret_cast<const float4*>(targ + tile * TILE_FLOATS);
            float4* sp = reinterpret_cast<float4*>(sm + stage * STAGE_FLOATS);
            float4* st = reinterpret_cast<float4*>(sm + stage * STAGE_FLOATS + TILE_FLOATS);
#pragma unroll
            for (int k = tid; k < TILE_V4; k += THREADS) {
                cp16(sp + k, p4 + k);
                cp16(st + k, t4 + k);
            }
        }
        cp_commit();  // commit (possibly empty) group to keep wait arithmetic uniform
    };

    // Prefetch 3 tiles ahead
    load_stage(0, 0);
    load_stage(1, 1);
    load_stage(2, 2);

    // Thread-pair split: half 0 handles boxes/IoU/conf, half 1 handles class term.
    const int half = tid >> 6;        // 0 or 1
    const int cell = tid & 63;        // cell within tile

    float acc = 0.f;
    for (int i = 0; i < iters; i++) {
        const int stage = i & (STAGES - 1);
        cp_wait2();          // <=2 groups pending -> stage i's copy complete
        __syncthreads();     // block-wide visibility of stage i

        const float* p = sm + stage * STAGE_FLOATS + cell * CH;
        const float* t = sm + stage * STAGE_FLOATS + TILE_FLOATS + cell * CH;
        const float t4v = t[4];

        if (half == 0) {
            // IoU of both pred boxes vs the target box
            const float tx0 = t[0], ty0 = t[1], tx1 = t[2], ty1 = t[3];
            const float area2 = (tx1 - tx0) * (ty1 - ty0);
            float iou0, iou1;
#pragma unroll
            for (int b = 0; b < 2; b++) {
                const int o = b * 5;
                const float x0 = p[o + 0], y0 = p[o + 1];
                const float x1 = p[o + 2], y1 = p[o + 3];
                float w = fminf(x1, tx1) - fmaxf(x0, tx0);
                float h = fminf(y1, ty1) - fmaxf(y0, ty0);
                w = fmaxf(w, 0.f);
                h = fmaxf(h, 0.f);
                const float inter = w * h;
                const float area1 = (x1 - x0) * (y1 - y0);
                const float iou = inter / (area1 + area2 - inter);
                if (b == 0) iou0 = iou; else iou1 = iou;
            }
            // argmax with first-index tiebreak: box 0 wins unless iou1 strictly greater
            const int o = (iou1 > iou0) ? 5 : 0;

            const float dx = p[o + 0] - t[o + 0];
            const float dy = p[o + 1] - t[o + 1];
            const float l1 = dx * dx + dy * dy;

            const float dw = sqrtf(p[o + 2]) - sqrtf(t[o + 2]);
            const float dh = sqrtf(p[o + 3]) - sqrtf(t[o + 3]);
            const float l2 = dw * dw + dh * dh;

            const float dc = p[o + 4] - t[o + 4];
            const float conf = dc * dc;

            if (t4v > 0.f)       acc += 5.0f * (l1 + l2) + conf;  // obj
            else if (t4v == 0.f) acc += 0.5f * conf;              // noobj
        } else {
            // class-probability term (only contributes when obj)
            if (t4v > 0.f) {
                float s5 = 0.f;
#pragma unroll
                for (int c = 10; c < 30; c++) {
                    const float d = p[c] - t[c];
                    s5 += d * d;
                }
                acc += s5;
            }
        }

        __syncthreads();                          // stage free before overwrite
        load_stage(i + 3, (i + 3) & (STAGES - 1)); // deep prefetch into freed stage
    }

    // ---- block reduction ---------------------------------------------------
    __syncthreads();              // smem free for reuse
    float w = warp_reduce(acc);
    if ((tid & 31) == 0) sm[tid >> 5] = w;
    __syncthreads();
    __shared__ bool s_last;
    if (tid == 0) {
        float v = 0.f;
#pragma unroll
        for (int j = 0; j < THREADS / 32; j++) v += sm[j];
        g_partials[bid] = v;
        __threadfence();
        unsigned int old = atomicAdd(&g_count, 1u);
        s_last = (((old + 1u) % GRID) == 0u);   // wraps -> valid on every graph replay
    }
    __syncthreads();

    // ---- last block finishes the reduction (deterministic order) -----------
    if (s_last) {
        __threadfence();
        float v = 0.f;
        for (int k = tid; k < GRID; k += THREADS) v += g_partials[k];
        v = warp_reduce(v);
        if ((tid & 31) == 0) sm[tid >> 5] = v;
        __syncthreads();
        if (tid == 0) {
            float tot = 0.f;
#pragma unroll
            for (int j = 0; j < THREADS / 32; j++) tot += sm[j];
            out[0] = tot;
        }
        // d_out is poisoned to 0xAA; clear any extra elements
        for (int k = tid + 1; k < out_size; k += THREADS) out[k] = 0.f;
    }
}

extern "C" void kernel_launch(void* const* d_in, const int* in_sizes, int n_in,
                              void* d_out, int out_size) {
    const float* pred = (const float*)d_in[0];
    const float* targ = (const float*)d_in[1];
    float* out = (float*)d_out;
    const int n_cells = in_sizes[0] / CH;     // 1,605,632
    const int n_tiles = n_cells / CELLS;      // 25,088 (exact)

    const size_t smem = (size_t)STAGES * STAGE_FLOATS * sizeof(float);  // 61440 B
    cudaFuncSetAttribute(yolo_fused, cudaFuncAttributeMaxDynamicSharedMemorySize, (int)smem);

    yolo_fused<<<GRID, THREADS, smem>>>(pred, targ, n_tiles, out, out_size);
}

// round 6
// speedup vs baseline: 1.1236x; 1.0301x over previous
#include <cuda_runtime.h>

#define CH           30
#define CELLS        64
#define THREADS      128
#define STAGES       3
#define GRID         608                  // 152 SMs x 4 resident blocks (persistent)
#define TILE_FLOATS  (CELLS * CH)         // 1920 floats = 7680 B per array per tile
#define TILE_V4      (TILE_FLOATS / 4)    // 480 float4 per array per tile
#define STAGE_FLOATS (2 * TILE_FLOATS)    // pred + target per stage = 15360 B

// Deterministic scratch (no device-side allocation).
__device__ float        g_partials[GRID];
__device__ unsigned int g_count = 0;      // self-resetting mod GRID across graph replays

__device__ __forceinline__ void cp16(void* smem_dst, const void* gmem_src) {
    unsigned int d = (unsigned int)__cvta_generic_to_shared(smem_dst);
    asm volatile("cp.async.cg.shared.global [%0], [%1], 16;\n" :: "r"(d), "l"(gmem_src));
}
__device__ __forceinline__ void cp_commit() { asm volatile("cp.async.commit_group;\n" ::: "memory"); }
__device__ __forceinline__ void cp_wait1()  { asm volatile("cp.async.wait_group 1;\n" ::: "memory"); }

__device__ __forceinline__ float warp_reduce(float v) {
#pragma unroll
    for (int o = 16; o > 0; o >>= 1) v += __shfl_xor_sync(0xffffffffu, v, o);
    return v;
}

__global__ void __launch_bounds__(THREADS)
yolo_fused(const float* __restrict__ pred, const float* __restrict__ targ,
           int n_tiles, float* __restrict__ out, int out_size) {
    extern __shared__ float sm[];   // STAGES x (pred tile + target tile) = 46080 B
    const int tid = threadIdx.x;
    const int bid = blockIdx.x;

    // Tiles for this block: tile = bid + i*GRID, i in [0, iters)  (41 or 42)
    const int iters = (n_tiles - bid + GRID - 1) / GRID;

    auto load_stage = [&](int i, int stage) {
        if (i < iters) {
            const long long tile = bid + (long long)i * GRID;
            const float4* p4 = reinterpret_cast<const float4*>(pred + tile * TILE_FLOATS);
            const float4* t4 = reinterpret_cast<const float4*>(targ + tile * TILE_FLOATS);
            float4* sp = reinterpret_cast<float4*>(sm + stage * STAGE_FLOATS);
            float4* st = reinterpret_cast<float4*>(sm + stage * STAGE_FLOATS + TILE_FLOATS);
#pragma unroll
            for (int k = tid; k < TILE_V4; k += THREADS) {
                cp16(sp + k, p4 + k);
                cp16(st + k, t4 + k);
            }
        }
        cp_commit();  // commit (possibly empty) group to keep wait arithmetic uniform
    };

    // Prefetch 2 tiles ahead
    load_stage(0, 0);
    load_stage(1, 1);

    // Thread-pair split: half 0 handles boxes/IoU/conf, half 1 handles class term.
    const int half = tid >> 6;        // 0 or 1
    const int cell = tid & 63;        // cell within tile

    float acc = 0.f;
    int stage = 0;
    for (int i = 0; i < iters; i++) {
        cp_wait1();          // <=1 group pending -> stage i's copy complete
        __syncthreads();     // block-wide visibility of stage i.
                             // NOTE: also orders last reads of stage (i-1)%3 before
                             // load_stage(i+2) below overwrites it -> no 2nd barrier.

        const float* p = sm + stage * STAGE_FLOATS + cell * CH;
        const float* t = sm + stage * STAGE_FLOATS + TILE_FLOATS + cell * CH;
        const float t4v = t[4];

        if (half == 0) {
            // IoU of both pred boxes vs the target box
            const float tx0 = t[0], ty0 = t[1], tx1 = t[2], ty1 = t[3];
            const float area2 = (tx1 - tx0) * (ty1 - ty0);
            float iou0, iou1;
#pragma unroll
            for (int b = 0; b < 2; b++) {
                const int o = b * 5;
                const float x0 = p[o + 0], y0 = p[o + 1];
                const float x1 = p[o + 2], y1 = p[o + 3];
                float w = fminf(x1, tx1) - fmaxf(x0, tx0);
                float h = fminf(y1, ty1) - fmaxf(y0, ty0);
                w = fmaxf(w, 0.f);
                h = fmaxf(h, 0.f);
                const float inter = w * h;
                const float area1 = (x1 - x0) * (y1 - y0);
                const float iou = inter / (area1 + area2 - inter);
                if (b == 0) iou0 = iou; else iou1 = iou;
            }
            // argmax with first-index tiebreak: box 0 wins unless iou1 strictly greater
            const int o = (iou1 > iou0) ? 5 : 0;

            const float dx = p[o + 0] - t[o + 0];
            const float dy = p[o + 1] - t[o + 1];
            const float l1 = dx * dx + dy * dy;

            const float dw = sqrtf(p[o + 2]) - sqrtf(t[o + 2]);
            const float dh = sqrtf(p[o + 3]) - sqrtf(t[o + 3]);
            const float l2 = dw * dw + dh * dh;

            const float dc = p[o + 4] - t[o + 4];
            const float conf = dc * dc;

            if (t4v > 0.f)       acc += 5.0f * (l1 + l2) + conf;  // obj
            else if (t4v == 0.f) acc += 0.5f * conf;              // noobj
        } else {
            // class-probability term (only contributes when obj)
            if (t4v > 0.f) {
                float s5 = 0.f;
#pragma unroll
                for (int c = 10; c < 30; c++) {
                    const float d = p[c] - t[c];
                    s5 += d * d;
                }
                acc += s5;
            }
        }

        // Prefetch tile i+2 into the stage freed at iteration i-1 (safe: see barrier note)
        const int next = (stage + 2 >= STAGES) ? stage + 2 - STAGES : stage + 2;
        load_stage(i + 2, next);
        stage = (stage + 1 == STAGES) ? 0 : stage + 1;
    }

    // ---- block reduction ---------------------------------------------------
    __syncthreads();              // smem free for reuse
    float w = warp_reduce(acc);
    if ((tid & 31) == 0) sm[tid >> 5] = w;
    __syncthreads();
    __shared__ bool s_last;
    if (tid == 0) {
        float v = 0.f;
#pragma unroll
        for (int j = 0; j < THREADS / 32; j++) v += sm[j];
        g_partials[bid] = v;
        __threadfence();
        unsigned int old = atomicAdd(&g_count, 1u);
        s_last = (((old + 1u) % GRID) == 0u);   // wraps -> valid on every graph replay
    }
    __syncthreads();

    // ---- last block finishes the reduction (deterministic order) -----------
    if (s_last) {
        __threadfence();
        float v = 0.f;
        for (int k = tid; k < GRID; k += THREADS) v += g_partials[k];
        v = warp_reduce(v);
        if ((tid & 31) == 0) sm[tid >> 5] = v;
        __syncthreads();
        if (tid == 0) {
            float tot = 0.f;
#pragma unroll
            for (int j = 0; j < THREADS / 32; j++) tot += sm[j];
            out[0] = tot;
        }
        // d_out is poisoned to 0xAA; clear any extra elements
        for (int k = tid + 1; k < out_size; k += THREADS) out[k] = 0.f;
    }
}

extern "C" void kernel_launch(void* const* d_in, const int* in_sizes, int n_in,
                              void* d_out, int out_size) {
    const float* pred = (const float*)d_in[0];
    const float* targ = (const float*)d_in[1];
    float* out = (float*)d_out;
    const int n_cells = in_sizes[0] / CH;     // 1,605,632
    const int n_tiles = n_cells / CELLS;      // 25,088

    const size_t smem = (size_t)STAGES * STAGE_FLOATS * sizeof(float);  // 46080 B
    cudaFuncSetAttribute(yolo_fused, cudaFuncAttributeMaxDynamicSharedMemorySize, (int)smem);

    yolo_fused<<<GRID, THREADS, smem>>>(pred, targ, n_tiles, out, out_size);
}